// round 6
// baseline (speedup 1.0000x reference)
#include <cuda_runtime.h>
#include <math.h>

#define NB    128
#define H     128
#define NPG   8
#define BT    3
#define AA    243
#define PAIRS 192
#define TPB   512
#define PTST  132   // padded Pt row stride (floats)

typedef unsigned long long u64;

__device__ __forceinline__ u64 pack2(float lo, float hi) {
    u64 r; asm("mov.b64 %0, {%1, %2};" : "=l"(r) : "f"(lo), "f"(hi)); return r;
}
__device__ __forceinline__ void fma2(u64& d, u64 a, u64 b) {
    asm("fma.rn.f32x2 %0, %1, %2, %0;" : "+l"(d) : "l"(a), "l"(b));
}
__device__ __forceinline__ float2 unpack2(u64 v) {
    float2 f; asm("mov.b64 {%0, %1}, %2;" : "=f"(f.x), "=f"(f.y) : "l"(v)); return f;
}

__global__ __launch_bounds__(TPB, 1)
void fused_apm_kernel(const float* __restrict__ nf,      // (1024,128)
                      const float* __restrict__ mask,    // (128,243)
                      const float* __restrict__ Wfcv1,   // (128,64)
                      const float* __restrict__ bfcv1,   // (64)
                      const float* __restrict__ Wfcv2,   // (64,1)
                      const float* __restrict__ bfcv2,   // (1)
                      const float* __restrict__ Wa2,     // (256,128)
                      const float* __restrict__ ba2,     // (128)
                      const float* __restrict__ Wfin,    // (128,3)
                      const float* __restrict__ bfin,    // (3)
                      const int*   __restrict__ idxmask, // (128,243)
                      float* __restrict__ out)           // probs[128*243] ++ readout[128]
{
    const int b = blockIdx.x;
    const int t = threadIdx.x;

    __shared__ __align__(16) u64   ps8[4][H];              // packed relu'd node pairs
    __shared__ __align__(16) float Pt[2][2][NPG][PTST];    // GEMM partials [ch][grp][n][h]
    __shared__ __align__(16) float ssum[H];
    __shared__ __align__(16) float sba[H];
    __shared__ __align__(16) float sWfT[BT][H];
    __shared__ float sc[PAIRS];
    __shared__ int   sidx[AA];
    __shared__ float smk[AA];
    __shared__ float red[16];

    // ---- entry: launch all cold loads ----
    if (t < AA) {
        sidx[t] = idxmask[b * AA + t];
        smk[t]  = mask[b * AA + t];
    }
    {
        int n = t >> 8, c0 = (t & 255) * 2;           // wait—cover 1024 elems w/ 512 thr:
    }
    #pragma unroll
    for (int idx = t; idx < NPG * H; idx += TPB) {
        int n = idx >> 7, c = idx & 127;
        float v = fmaxf(nf[(b * NPG + n) * H + c], 0.f);
        reinterpret_cast<float*>(&ps8[n >> 1][c])[n & 1] = v;
    }
    if (t < H) {
        float a = 0.f;
        #pragma unroll
        for (int n = 0; n < NPG; n++) a += nf[(b * NPG + n) * H + t];
        ssum[t] = a;
        sba[t]  = ba2[t];
    } else if (t < H + H * BT) {
        int idx = t - H;
        int hh = idx & 127, k = idx >> 7;
        sWfT[k][hh] = Wfin[hh * BT + k];
    }
    __syncthreads();   // S1

    // ---- Ai/Bj GEMM: thread = (ch, grp, h); W in two 32-wide register batches ----
    {
        const int h   = t & 127;
        const int grp = (t >> 7) & 1;
        const int ch  = t >> 8;
        const float* Wp = Wa2 + grp * H * H + ch * 64 * H + h;
        u64 acc0 = 0, acc1 = 0, acc2 = 0, acc3 = 0;
        const ulonglong2* p0 = reinterpret_cast<const ulonglong2*>(&ps8[0][ch * 64]);
        const ulonglong2* p1 = reinterpret_cast<const ulonglong2*>(&ps8[1][ch * 64]);
        const ulonglong2* p2 = reinterpret_cast<const ulonglong2*>(&ps8[2][ch * 64]);
        const ulonglong2* p3 = reinterpret_cast<const ulonglong2*>(&ps8[3][ch * 64]);
        #pragma unroll
        for (int half = 0; half < 2; half++) {
            float Wr[32];
            #pragma unroll
            for (int i = 0; i < 32; i++)              // 32 independent LDGs, front-batched
                Wr[i] = Wp[(half * 32 + i) * H];
            #pragma unroll
            for (int cc = 0; cc < 32; cc += 2) {
                const int cg = half * 32 + cc;
                u64 wp0 = pack2(Wr[cc],     Wr[cc]);
                u64 wp1 = pack2(Wr[cc + 1], Wr[cc + 1]);
                ulonglong2 q;
                q = p0[cg >> 1]; fma2(acc0, q.x, wp0); fma2(acc0, q.y, wp1);
                q = p1[cg >> 1]; fma2(acc1, q.x, wp0); fma2(acc1, q.y, wp1);
                q = p2[cg >> 1]; fma2(acc2, q.x, wp0); fma2(acc2, q.y, wp1);
                q = p3[cg >> 1]; fma2(acc3, q.x, wp0); fma2(acc3, q.y, wp1);
            }
        }
        float2 f;
        f = unpack2(acc0); Pt[ch][grp][0][h] = f.x; Pt[ch][grp][1][h] = f.y;
        f = unpack2(acc1); Pt[ch][grp][2][h] = f.x; Pt[ch][grp][3][h] = f.y;
        f = unpack2(acc2); Pt[ch][grp][4][h] = f.x; Pt[ch][grp][5][h] = f.y;
        f = unpack2(acc3); Pt[ch][grp][6][h] = f.x; Pt[ch][grp][7][h] = f.y;
    }
    __syncthreads();   // S2

    // ---- pair scores read BOTH c-half partials directly (no reduce phase) ----
    if (t < 2 * PAIRS) {
        const int sid  = t >> 1;
        const int half = t & 1;
        const int k = sid >> 6;
        const int p = sid & 63;
        const int i = p >> 3, j = p & 7;
        const float4* A04 = reinterpret_cast<const float4*>(Pt[0][0][i]);
        const float4* A14 = reinterpret_cast<const float4*>(Pt[1][0][i]);
        const float4* B04 = reinterpret_cast<const float4*>(Pt[0][1][j]);
        const float4* B14 = reinterpret_cast<const float4*>(Pt[1][1][j]);
        const float4* W4  = reinterpret_cast<const float4*>(sWfT[k]);
        const float4* Z4  = reinterpret_cast<const float4*>(sba);
        float acc0 = 0.f, acc1 = 0.f;
        const int hb = half * 16;
        #pragma unroll
        for (int q = 0; q < 16; q += 2) {
            float4 a0, a1, b0, b1, w, z;
            a0 = A04[hb + q]; a1 = A14[hb + q];
            b0 = B04[hb + q]; b1 = B14[hb + q];
            w  = W4[hb + q];  z  = Z4[hb + q];
            acc0 += fmaxf((a0.x + a1.x) + (b0.x + b1.x) + z.x, 0.f) * w.x
                  + fmaxf((a0.y + a1.y) + (b0.y + b1.y) + z.y, 0.f) * w.y
                  + fmaxf((a0.z + a1.z) + (b0.z + b1.z) + z.z, 0.f) * w.z
                  + fmaxf((a0.w + a1.w) + (b0.w + b1.w) + z.w, 0.f) * w.w;
            a0 = A04[hb + q + 1]; a1 = A14[hb + q + 1];
            b0 = B04[hb + q + 1]; b1 = B14[hb + q + 1];
            w  = W4[hb + q + 1];  z  = Z4[hb + q + 1];
            acc1 += fmaxf((a0.x + a1.x) + (b0.x + b1.x) + z.x, 0.f) * w.x
                  + fmaxf((a0.y + a1.y) + (b0.y + b1.y) + z.y, 0.f) * w.y
                  + fmaxf((a0.z + a1.z) + (b0.z + b1.z) + z.z, 0.f) * w.z
                  + fmaxf((a0.w + a1.w) + (b0.w + b1.w) + z.w, 0.f) * w.w;
        }
        float acc = acc0 + acc1;
        acc += __shfl_xor_sync(0xffffffffu, acc, 1);
        if (half == 0) sc[p * BT + k] = acc + bfin[k];
    } else {
        const int u    = t - 2 * PAIRS;
        const int j    = u >> 1;
        const int half = u & 1;
        const float4* S4 = reinterpret_cast<const float4*>(ssum);
        float acc0 = 0.f, acc1 = 0.f;
        const int cb = half * 16;
        #pragma unroll
        for (int q = 0; q < 16; q += 2) {
            float4 sv = S4[cb + q];
            int c = (cb + q) * 4;
            acc0 += sv.x * Wfcv1[(c + 0) * 64 + j] + sv.y * Wfcv1[(c + 1) * 64 + j]
                  + sv.z * Wfcv1[(c + 2) * 64 + j] + sv.w * Wfcv1[(c + 3) * 64 + j];
            sv = S4[cb + q + 1];
            c = (cb + q + 1) * 4;
            acc1 += sv.x * Wfcv1[(c + 0) * 64 + j] + sv.y * Wfcv1[(c + 1) * 64 + j]
                  + sv.z * Wfcv1[(c + 2) * 64 + j] + sv.w * Wfcv1[(c + 3) * 64 + j];
        }
        float tot = acc0 + acc1;
        tot += __shfl_xor_sync(0xffffffffu, tot, 1);
        float hid = (half == 0) ? fmaxf(tot + bfcv1[j], 0.f) * Wfcv2[j] : 0.f;
        #pragma unroll
        for (int off = 16; off > 0; off >>= 1)
            hid += __shfl_down_sync(0xffffffffu, hid, off);
        if ((t & 31) == 0) red[t >> 5] = hid;          // red[12..15]
    }
    __syncthreads();   // S3: sc + red visible

    // ---- warp 0 finishes everything; warps 1-15 retire ----
    if (t < 32) {
        if (t == 0)
            out[NB * AA + b] = ((red[12] + red[13]) + (red[14] + red[15])) + bfcv2[0];

        float fv[8];
        #pragma unroll
        for (int q = 0; q < 8; q++) {
            int e = t + 32 * q;
            if (e < AA) {
                int im = sidx[e];
                fv[q] = ((im < PAIRS) ? sc[im] : 0.f) + smk[e];
            } else fv[q] = -INFINITY;
        }
        float m = fv[0];
        #pragma unroll
        for (int q = 1; q < 8; q++) m = fmaxf(m, fv[q]);
        #pragma unroll
        for (int off = 16; off > 0; off >>= 1)
            m = fmaxf(m, __shfl_xor_sync(0xffffffffu, m, off));
        float sr = 0.f;
        #pragma unroll
        for (int q = 0; q < 8; q++) {
            fv[q] = (fv[q] == -INFINITY) ? 0.f : __expf(fv[q] - m);
            sr += fv[q];
        }
        #pragma unroll
        for (int off = 16; off > 0; off >>= 1)
            sr += __shfl_xor_sync(0xffffffffu, sr, off);
        float inv = 1.f / sr;
        #pragma unroll
        for (int q = 0; q < 8; q++) {
            int e = t + 32 * q;
            if (e < AA) out[b * AA + e] = fv[q] * inv;
        }
    }
}

extern "C" void kernel_launch(void* const* d_in, const int* in_sizes, int n_in,
                              void* d_out, int out_size) {
    const float* nf     = (const float*)d_in[0];
    const float* mask   = (const float*)d_in[2];
    const float* Wfcv1  = (const float*)d_in[3];
    const float* bfcv1  = (const float*)d_in[4];
    const float* Wfcv2  = (const float*)d_in[5];
    const float* bfcv2  = (const float*)d_in[6];
    const float* Wa2    = (const float*)d_in[7];
    const float* ba2    = (const float*)d_in[8];
    const float* Wfin   = (const float*)d_in[9];
    const float* bfin   = (const float*)d_in[10];
    const int*   idxm   = (const int*)d_in[11];
    float* out = (float*)d_out;

    fused_apm_kernel<<<NB, TPB>>>(nf, mask, Wfcv1, bfcv1, Wfcv2, bfcv2,
                                  Wa2, ba2, Wfin, bfin, idxm, out);
}

// round 7
// speedup vs baseline: 1.0698x; 1.0698x over previous
#include <cuda_runtime.h>
#include <math.h>

#define NB    128
#define H     128
#define NPG   8
#define BT    3
#define AA    243
#define PAIRS 192
#define TPB   512
#define ABST  132

typedef unsigned long long u64;

__device__ __forceinline__ u64 pack2(float lo, float hi) {
    u64 r; asm("mov.b64 %0, {%1, %2};" : "=l"(r) : "f"(lo), "f"(hi)); return r;
}
__device__ __forceinline__ void fma2(u64& d, u64 a, u64 b) {
    asm("fma.rn.f32x2 %0, %1, %2, %0;" : "+l"(d) : "l"(a), "l"(b));
}
__device__ __forceinline__ float2 unpack2(u64 v) {
    float2 f; asm("mov.b64 {%0, %1}, %2;" : "=f"(f.x), "=f"(f.y) : "l"(v)); return f;
}

__global__ __launch_bounds__(TPB, 1)
void fused_apm_kernel(const float* __restrict__ nf,      // (1024,128)
                      const float* __restrict__ mask,    // (128,243)
                      const float* __restrict__ Wfcv1,   // (128,64)
                      const float* __restrict__ bfcv1,   // (64)
                      const float* __restrict__ Wfcv2,   // (64,1)
                      const float* __restrict__ bfcv2,   // (1)
                      const float* __restrict__ Wa2,     // (256,128)
                      const float* __restrict__ ba2,     // (128)
                      const float* __restrict__ Wfin,    // (128,3)
                      const float* __restrict__ bfin,    // (3)
                      const int*   __restrict__ idxmask, // (128,243)
                      float* __restrict__ out)           // probs[128*243] ++ readout[128]
{
    const int b = blockIdx.x;
    const int t = threadIdx.x;

    __shared__ __align__(16) u64   ps[H][4];           // [c][node-pair], 4KB
    __shared__ __align__(16) float AB[2][NPG][ABST];   // FINAL Ai/Bj (no partials)
    __shared__ __align__(16) float ssum[H];
    __shared__ __align__(16) float sba[H];
    __shared__ __align__(16) float sWfT[BT][H];
    __shared__ float sc[PAIRS];
    __shared__ int   sidx[AA];
    __shared__ float smk[AA];
    __shared__ float red[16];

    // GEMM mapping (needed early for W prefetch)
    const int h   = t & 127;
    const int grp = (t >> 7) & 1;
    const int X   = t >> 8;                       // node-quad: nodes 4X..4X+3
    const float* Wp = Wa2 + grp * H * H + h;

    // ---- entry: launch every cold load stream ----
    if (t < AA) {
        sidx[t] = idxmask[b * AA + t];
        smk[t]  = mask[b * AA + t];
    }
    if (t >= 384) {                               // warm Wfcv1 into L2 (cheap)
        const char* base = (const char*)Wfcv1;
        int u = t - 384;
        asm volatile("prefetch.global.L2 [%0];" :: "l"(base + (u * 2 + 0) * 128));
        asm volatile("prefetch.global.L2 [%0];" :: "l"(base + (u * 2 + 1) * 128));
    }
    float Wr[32];                                 // first W batch before the barrier
    #pragma unroll
    for (int i = 0; i < 32; i++) Wr[i] = Wp[i * H];

    // ---- stage node features: ps[c][pair] layout, coalesced LDG ----
    {
        const int c  = t & 127;
        const int nh = t >> 7;                    // pair index 0..3
        float v0 = fmaxf(nf[(b * NPG + 2 * nh)     * H + c], 0.f);
        float v1 = fmaxf(nf[(b * NPG + 2 * nh + 1) * H + c], 0.f);
        ps[c][nh] = pack2(v0, v1);
    }
    if (t < H) {
        float a = 0.f;
        #pragma unroll
        for (int n = 0; n < NPG; n++) a += nf[(b * NPG + n) * H + t];
        ssum[t] = a;
        sba[t]  = ba2[t];
    } else if (t < H + H * BT) {
        int idx = t - H;
        int hh = idx & 127, k = idx >> 7;
        sWfT[k][hh] = Wfin[hh * BT + k];
    }
    __syncthreads();   // S1

    // ---- Ai/Bj GEMM: full c per thread, 1 LDS.128/c, final output ----
    {
        u64 acc0 = 0, acc1 = 0;                   // pairs 2X, 2X+1
        #pragma unroll
        for (int batch = 0; batch < 4; batch++) {
            if (batch) {                          // batches 1-3: load 32 W regs (MLP=32)
                #pragma unroll
                for (int i = 0; i < 32; i++) Wr[i] = Wp[(batch * 32 + i) * H];
            }
            #pragma unroll
            for (int cc = 0; cc < 32; cc++) {
                const int c = batch * 32 + cc;
                u64 wp = pack2(Wr[cc], Wr[cc]);
                ulonglong2 q = *reinterpret_cast<const ulonglong2*>(&ps[c][X * 2]);
                fma2(acc0, q.x, wp);
                fma2(acc1, q.y, wp);
            }
        }
        float2 f;
        f = unpack2(acc0); AB[grp][4 * X + 0][h] = f.x; AB[grp][4 * X + 1][h] = f.y;
        f = unpack2(acc1); AB[grp][4 * X + 2][h] = f.x; AB[grp][4 * X + 3][h] = f.y;
    }
    __syncthreads();   // S2

    // ---- pair scores (t<384, 2 threads/score, lean 4-vector reads) + readout ----
    if (t < 2 * PAIRS) {
        const int sid  = t >> 1;
        const int half = t & 1;
        const int k = sid >> 6;
        const int p = sid & 63;
        const int i = p >> 3, j = p & 7;
        const float4* A4 = reinterpret_cast<const float4*>(AB[0][i]);
        const float4* B4 = reinterpret_cast<const float4*>(AB[1][j]);
        const float4* W4 = reinterpret_cast<const float4*>(sWfT[k]);
        const float4* Z4 = reinterpret_cast<const float4*>(sba);
        float acc0 = 0.f, acc1 = 0.f;
        const int hb = half * 16;
        #pragma unroll
        for (int q = 0; q < 16; q += 2) {
            float4 a, bb, w, z;
            a = A4[hb + q]; bb = B4[hb + q]; w = W4[hb + q]; z = Z4[hb + q];
            acc0 += fmaxf(a.x + bb.x + z.x, 0.f) * w.x
                  + fmaxf(a.y + bb.y + z.y, 0.f) * w.y
                  + fmaxf(a.z + bb.z + z.z, 0.f) * w.z
                  + fmaxf(a.w + bb.w + z.w, 0.f) * w.w;
            a = A4[hb + q + 1]; bb = B4[hb + q + 1]; w = W4[hb + q + 1]; z = Z4[hb + q + 1];
            acc1 += fmaxf(a.x + bb.x + z.x, 0.f) * w.x
                  + fmaxf(a.y + bb.y + z.y, 0.f) * w.y
                  + fmaxf(a.z + bb.z + z.z, 0.f) * w.z
                  + fmaxf(a.w + bb.w + z.w, 0.f) * w.w;
        }
        float acc = acc0 + acc1;
        acc += __shfl_xor_sync(0xffffffffu, acc, 1);
        if (half == 0) sc[p * BT + k] = acc + bfin[k];
    } else {
        const int u    = t - 2 * PAIRS;
        const int j    = u >> 1;
        const int half = u & 1;
        const float4* S4 = reinterpret_cast<const float4*>(ssum);
        float acc0 = 0.f, acc1 = 0.f;
        const int cb = half * 16;
        #pragma unroll
        for (int q = 0; q < 16; q += 2) {
            float4 sv = S4[cb + q];
            int c = (cb + q) * 4;
            acc0 += sv.x * Wfcv1[(c + 0) * 64 + j] + sv.y * Wfcv1[(c + 1) * 64 + j]
                  + sv.z * Wfcv1[(c + 2) * 64 + j] + sv.w * Wfcv1[(c + 3) * 64 + j];
            sv = S4[cb + q + 1];
            c = (cb + q + 1) * 4;
            acc1 += sv.x * Wfcv1[(c + 0) * 64 + j] + sv.y * Wfcv1[(c + 1) * 64 + j]
                  + sv.z * Wfcv1[(c + 2) * 64 + j] + sv.w * Wfcv1[(c + 3) * 64 + j];
        }
        float tot = acc0 + acc1;
        tot += __shfl_xor_sync(0xffffffffu, tot, 1);
        float hid = (half == 0) ? fmaxf(tot + bfcv1[j], 0.f) * Wfcv2[j] : 0.f;
        #pragma unroll
        for (int off = 16; off > 0; off >>= 1)
            hid += __shfl_down_sync(0xffffffffu, hid, off);
        if ((t & 31) == 0) red[t >> 5] = hid;     // red[12..15]
    }
    __syncthreads();   // S3

    // ---- warp 0 finishes softmax + readout store; other warps retire ----
    if (t < 32) {
        if (t == 0)
            out[NB * AA + b] = ((red[12] + red[13]) + (red[14] + red[15])) + bfcv2[0];

        float fv[8];
        #pragma unroll
        for (int q = 0; q < 8; q++) {
            int e = t + 32 * q;
            if (e < AA) {
                int im = sidx[e];
                fv[q] = ((im < PAIRS) ? sc[im] : 0.f) + smk[e];
            } else fv[q] = -INFINITY;
        }
        float m = fv[0];
        #pragma unroll
        for (int q = 1; q < 8; q++) m = fmaxf(m, fv[q]);
        #pragma unroll
        for (int off = 16; off > 0; off >>= 1)
            m = fmaxf(m, __shfl_xor_sync(0xffffffffu, m, off));
        float sr = 0.f;
        #pragma unroll
        for (int q = 0; q < 8; q++) {
            fv[q] = (fv[q] == -INFINITY) ? 0.f : __expf(fv[q] - m);
            sr += fv[q];
        }
        #pragma unroll
        for (int off = 16; off > 0; off >>= 1)
            sr += __shfl_xor_sync(0xffffffffu, sr, off);
        float inv = 1.f / sr;
        #pragma unroll
        for (int q = 0; q < 8; q++) {
            int e = t + 32 * q;
            if (e < AA) out[b * AA + e] = fv[q] * inv;
        }
    }
}

extern "C" void kernel_launch(void* const* d_in, const int* in_sizes, int n_in,
                              void* d_out, int out_size) {
    const float* nf     = (const float*)d_in[0];
    const float* mask   = (const float*)d_in[2];
    const float* Wfcv1  = (const float*)d_in[3];
    const float* bfcv1  = (const float*)d_in[4];
    const float* Wfcv2  = (const float*)d_in[5];
    const float* bfcv2  = (const float*)d_in[6];
    const float* Wa2    = (const float*)d_in[7];
    const float* ba2    = (const float*)d_in[8];
    const float* Wfin   = (const float*)d_in[9];
    const float* bfin   = (const float*)d_in[10];
    const int*   idxm   = (const int*)d_in[11];
    float* out = (float*)d_out;

    fused_apm_kernel<<<NB, TPB>>>(nf, mask, Wfcv1, bfcv1, Wfcv2, bfcv2,
                                  Wa2, ba2, Wfin, bfin, idxm, out);
}